// round 1
// baseline (speedup 1.0000x reference)
#include <cuda_runtime.h>
#include <math.h>

#define NB 8
#define NC 256
#define L1V 1024
#define L2V 256
#define L3V 64

// ---------------- scratch (static device arrays; no allocation) ----------------
__device__ float g_xz [NB*L1V*512];
__device__ float g_f1 [NB*L1V*NC];
__device__ float g_f2 [NB*L2V*NC];
__device__ float g_f3 [NB*L3V*NC];
__device__ float g_xd1f[NB*L1V*40];
__device__ float g_xd1b[NB*L1V*40];
__device__ float g_xd2 [NB*L2V*40];
__device__ float g_xd3 [NB*L3V*40];
__device__ float g_yf1[NB*L1V*NC];
__device__ float g_yb1[NB*L1V*NC];
__device__ float g_yf2[NB*L2V*NC];
__device__ float g_yb2[NB*L2V*NC];
__device__ float g_yf3[NB*L3V*NC];
__device__ float g_yb3[NB*L3V*NC];
__device__ float g_y3 [NB*L3V*NC];
__device__ float g_y2 [NB*L2V*NC];
__device__ float g_y1m[NB*L1V*NC];

// ---------------- SGEMM: C[m][n] = sum_k A[m][k]*W[n][k] + bias[n] ----------------
// A address = (m>>10)*a_bstride + (m&1023)*a_ms + k*a_ks   (per-batch rows = 1024 always)
// chw_out: C index = (m>>10)*N*1024 + n*1024 + (m&1023); else C[m*N + n]
#define BM 128
#define BN 128
#define BKK 8
__global__ __launch_bounds__(256) void sgemm_bias(
    const float* __restrict__ A, int a_ms, int a_ks, long long a_bstride,
    const float* __restrict__ W, const float* __restrict__ bias,
    float* __restrict__ C, int M, int N, int K, int chw_out)
{
    __shared__ float As[BKK][BM];
    __shared__ float Ws[BKK][BN];
    int tid = threadIdx.x;
    int bn = blockIdx.x * BN;
    int bm = blockIdx.y * BM;
    int tx = tid & 15;      // n direction
    int ty = tid >> 4;      // m direction
    float acc[8][8];
#pragma unroll
    for (int i = 0; i < 8; i++)
#pragma unroll
        for (int j = 0; j < 8; j++) acc[i][j] = 0.f;

    for (int k0 = 0; k0 < K; k0 += BKK) {
        if (a_ms == 1) {
            int m  = bm + (tid & 127);
            long long base = (long long)(m >> 10) * a_bstride + (m & 1023);
            int kk = (tid >> 7) * 4;
#pragma unroll
            for (int i = 0; i < 4; i++)
                As[kk + i][tid & 127] = A[base + (long long)(k0 + kk + i) * a_ks];
        } else {
            int m  = bm + (tid >> 1);
            long long base = (long long)(m >> 10) * a_bstride + (long long)(m & 1023) * a_ms;
            int kk = (tid & 1) * 4;
            float4 v = *reinterpret_cast<const float4*>(A + base + k0 + kk);
            As[kk + 0][tid >> 1] = v.x;
            As[kk + 1][tid >> 1] = v.y;
            As[kk + 2][tid >> 1] = v.z;
            As[kk + 3][tid >> 1] = v.w;
        }
        {
            int n  = bn + (tid >> 1);
            int kk = (tid & 1) * 4;
            float4 v = *reinterpret_cast<const float4*>(W + (long long)n * K + k0 + kk);
            Ws[kk + 0][tid >> 1] = v.x;
            Ws[kk + 1][tid >> 1] = v.y;
            Ws[kk + 2][tid >> 1] = v.z;
            Ws[kk + 3][tid >> 1] = v.w;
        }
        __syncthreads();
#pragma unroll
        for (int kk = 0; kk < BKK; kk++) {
            float a[8], b[8];
#pragma unroll
            for (int i = 0; i < 8; i++) a[i] = As[kk][ty * 8 + i];
#pragma unroll
            for (int j = 0; j < 8; j++) b[j] = Ws[kk][tx * 8 + j];
#pragma unroll
            for (int i = 0; i < 8; i++)
#pragma unroll
                for (int j = 0; j < 8; j++) acc[i][j] = fmaf(a[i], b[j], acc[i][j]);
        }
        __syncthreads();
    }
#pragma unroll
    for (int i = 0; i < 8; i++) {
        int m = bm + ty * 8 + i;
        if (chw_out) {
#pragma unroll
            for (int j = 0; j < 8; j++) {
                int n = bn + tx * 8 + j;
                C[(long long)(m >> 10) * N * 1024 + (long long)n * 1024 + (m & 1023)] =
                    acc[i][j] + bias[n];
            }
        } else {
            int n0 = bn + tx * 8;
#pragma unroll
            for (int j = 0; j < 8; j++)
                C[(long long)m * N + n0 + j] = acc[i][j] + bias[n0 + j];
        }
    }
}

// ---------------- 2x2 stride-2 conv, 256->256 channels, channel-last ----------------
#define BPc 8
__global__ __launch_bounds__(256) void conv2s2(
    const float* __restrict__ in, const float* __restrict__ w,
    const float* __restrict__ bias, float* __restrict__ out,
    int Win, int Wout)
{
    __shared__ __align__(16) float s[BPc][256][4];   // [p][c][q]
    int b  = blockIdx.y;
    int p0 = blockIdx.x * BPc;
    int tid = threadIdx.x;
    const float* inb = in + (long long)b * Win * Win * 256;
    for (int idx = tid; idx < BPc * 4 * 256; idx += 256) {
        int p = idx >> 10;
        int q = (idx >> 8) & 3;
        int c = idx & 255;
        int op = p0 + p;
        int i  = op / Wout, j = op % Wout;
        int dy = q >> 1, dx = q & 1;
        int l  = (2 * i + dy) * Win + (2 * j + dx);
        s[p][c][q] = inb[(long long)l * 256 + c];
    }
    __syncthreads();
    int o = tid;
    float acc[BPc];
#pragma unroll
    for (int p = 0; p < BPc; p++) acc[p] = 0.f;
    const float4* w4 = reinterpret_cast<const float4*>(w + (long long)o * 1024);
    for (int c = 0; c < 256; c++) {
        float4 wq = w4[c];
#pragma unroll
        for (int p = 0; p < BPc; p++) {
            float4 sq = *reinterpret_cast<const float4*>(&s[p][c][0]);
            acc[p] = fmaf(sq.x, wq.x, acc[p]);
            acc[p] = fmaf(sq.y, wq.y, acc[p]);
            acc[p] = fmaf(sq.z, wq.z, acc[p]);
            acc[p] = fmaf(sq.w, wq.w, acc[p]);
        }
    }
    float bo = bias[o];
#pragma unroll
    for (int p = 0; p < BPc; p++)
        out[(long long)b * Wout * Wout * 256 + (long long)(p0 + p) * 256 + o] = acc[p] + bo;
}

// ---------------- xd[b,l,k] = sum_d f[b,l,d] * xw[k,d],  k<40 ----------------
__global__ __launch_bounds__(256) void xd_kernel(
    const float* __restrict__ f, const float* __restrict__ xw, float* __restrict__ xd)
{
    __shared__ float row[256];
    long long bl = blockIdx.x;
    row[threadIdx.x] = f[bl * 256 + threadIdx.x];
    __syncthreads();
    int warp = threadIdx.x >> 5, lane = threadIdx.x & 31;
#pragma unroll
    for (int kk = 0; kk < 5; kk++) {
        int k = warp * 5 + kk;
        float s = 0.f;
#pragma unroll
        for (int e = 0; e < 8; e++)
            s = fmaf(row[lane + 32 * e], xw[k * 256 + lane + 32 * e], s);
#pragma unroll
        for (int off = 16; off; off >>= 1) s += __shfl_down_sync(0xffffffffu, s, off);
        if (lane == 0) xd[bl * 40 + k] = s;
    }
}

// ---------------- selective scan: 384 blocks x 32 threads ----------------
// block layout: [0,128): level1, [128,256): level2, [256,384): level3
// within level: dir = (r>>6), b = (r>>3)&7, chunk = r&7  (d = chunk*32+lane)
__global__ __launch_bounds__(32) void scan_kernel(
    const float* __restrict__ dtw1, const float* __restrict__ dtb1,
    const float* __restrict__ Al1,  const float* __restrict__ Dv1,
    const float* __restrict__ dtw2, const float* __restrict__ dtb2,
    const float* __restrict__ Al2,  const float* __restrict__ Dv2,
    const float* __restrict__ dtw3, const float* __restrict__ dtb3,
    const float* __restrict__ Al3,  const float* __restrict__ Dv3)
{
    int bx   = blockIdx.x;
    int lvl  = bx >> 7;
    int r    = bx & 127;
    int dir  = r >> 6;
    int b    = (r >> 3) & 7;
    int lane = threadIdx.x;
    int d    = (r & 7) * 32 + lane;

    const float *f, *xd, *dtw, *dtb, *Al, *Dv;
    float* y;
    int L;
    if (lvl == 0) {
        L = L1V; f = g_f1;
        xd = dir ? g_xd1b : g_xd1f;
        y  = dir ? g_yb1  : g_yf1;
        if (dir) { dtw = dtw2; dtb = dtb2; Al = Al2; Dv = Dv2; }
        else     { dtw = dtw1; dtb = dtb1; Al = Al1; Dv = Dv1; }
    } else if (lvl == 1) {
        L = L2V; f = g_f2; xd = g_xd2;
        y = dir ? g_yb2 : g_yf2;
        dtw = dtw2; dtb = dtb2; Al = Al2; Dv = Dv2;
    } else {
        L = L3V; f = g_f3; xd = g_xd3;
        y = dir ? g_yb3 : g_yf3;
        dtw = dtw3; dtb = dtb3; Al = Al3; Dv = Dv3;
    }
    f  += (long long)b * L * 256;
    xd += (long long)b * L * 40;
    y  += (long long)b * L * 256;

    float w[8];
#pragma unroll
    for (int rr = 0; rr < 8; rr++) w[rr] = dtw[d * 8 + rr];
    float bdt = dtb[d];
    float Areg[16];
#pragma unroll
    for (int n = 0; n < 16; n++) Areg[n] = -expf(Al[d * 16 + n]);
    float Dvv = Dv[d];
    float h[16];
#pragma unroll
    for (int n = 0; n < 16; n++) h[n] = 0.f;

    __shared__ float sxd[8][40];

    for (int s0 = 0; s0 < L; s0 += 8) {
        __syncwarp();
        for (int t = lane; t < 320; t += 32) {
            int ss = t / 40, kk = t - ss * 40;
            int l = dir ? (L - 1 - (s0 + ss)) : (s0 + ss);
            sxd[ss][kk] = xd[(long long)l * 40 + kk];
        }
        float xa[8];
#pragma unroll
        for (int ss = 0; ss < 8; ss++) {
            int l = dir ? (L - 1 - (s0 + ss)) : (s0 + ss);
            xa[ss] = f[(long long)l * 256 + d];
        }
        __syncwarp();
#pragma unroll
        for (int ss = 0; ss < 8; ss++) {
            float delta = bdt;
#pragma unroll
            for (int rr = 0; rr < 8; rr++) delta = fmaf(sxd[ss][rr], w[rr], delta);
            // softplus: max(x,0) + log1p(exp(-|x|))
            delta = fmaxf(delta, 0.f) + log1pf(__expf(-fabsf(delta)));
            float dxv = delta * xa[ss];
            float yv = 0.f;
#pragma unroll
            for (int n = 0; n < 16; n++) {
                float dA = __expf(delta * Areg[n]);
                h[n] = fmaf(h[n], dA, dxv * sxd[ss][8 + n]);
                yv = fmaf(h[n], sxd[ss][24 + n], yv);
            }
            yv = fmaf(xa[ss], Dvv, yv);
            int l = dir ? (L - 1 - (s0 + ss)) : (s0 + ss);
            y[(long long)l * 256 + d] = yv;
        }
    }
}

// ---------------- LayerNorm(fwd)+LayerNorm(bwd) + optional upsample-add + optional silu(z) ----------------
__global__ __launch_bounds__(256) void ln_kernel(
    const float* __restrict__ yf, const float* __restrict__ yb,
    const float* __restrict__ gf, const float* __restrict__ bef,
    const float* __restrict__ gb, const float* __restrict__ beb,
    const float* __restrict__ up, int upSrcW, int dstW,
    const float* __restrict__ z, float* __restrict__ out, int L)
{
    __shared__ float red[4][8];
    int bl = blockIdx.x;
    int b  = bl / L;
    int l  = bl - b * L;
    int c  = threadIdx.x;
    long long idx = (long long)bl * 256 + c;
    float vf = yf[idx], vb = yb[idx];

    float s0 = vf, s1 = vf * vf, s2 = vb, s3 = vb * vb;
#pragma unroll
    for (int off = 16; off; off >>= 1) {
        s0 += __shfl_down_sync(0xffffffffu, s0, off);
        s1 += __shfl_down_sync(0xffffffffu, s1, off);
        s2 += __shfl_down_sync(0xffffffffu, s2, off);
        s3 += __shfl_down_sync(0xffffffffu, s3, off);
    }
    int warp = c >> 5, lane = c & 31;
    if (lane == 0) { red[0][warp] = s0; red[1][warp] = s1; red[2][warp] = s2; red[3][warp] = s3; }
    __syncthreads();
    float sf = 0.f, sf2 = 0.f, sb = 0.f, sb2 = 0.f;
#pragma unroll
    for (int wv = 0; wv < 8; wv++) {
        sf += red[0][wv]; sf2 += red[1][wv]; sb += red[2][wv]; sb2 += red[3][wv];
    }
    const float inv = 1.f / 256.f;
    float muf = sf * inv, varf = sf2 * inv - muf * muf;
    float mub = sb * inv, varb = sb2 * inv - mub * mub;
    float nf = (vf - muf) * rsqrtf(varf + 1e-5f) * gf[c] + bef[c];
    float nb = (vb - mub) * rsqrtf(varb + 1e-5f) * gb[c] + beb[c];
    float v = nf + nb;
    if (up) {
        int i = l / dstW, j = l - (l / dstW) * dstW;
        v += up[((long long)b * upSrcW * upSrcW + (i >> 1) * upSrcW + (j >> 1)) * 256 + c];
    }
    if (z) {
        float zz = z[(long long)bl * 512 + 256 + c];
        v *= zz / (1.f + __expf(-zz));
    }
    out[idx] = v;
}

// ---------------- launch ----------------
extern "C" void kernel_launch(void* const* d_in, const int* in_sizes, int n_in,
                              void* d_out, int out_size)
{
    const float* input_f = (const float*)d_in[0];
    const float* in_w  = (const float*)d_in[1];
    const float* in_b  = (const float*)d_in[2];
    const float* c1_w  = (const float*)d_in[3];
    const float* c1_b  = (const float*)d_in[4];
    const float* c2_w  = (const float*)d_in[5];
    const float* c2_b  = (const float*)d_in[6];
    const float* c3_w  = (const float*)d_in[7];
    const float* c3_b  = (const float*)d_in[8];
    const float* out_w = (const float*)d_in[9];
    const float* out_b = (const float*)d_in[10];
    const float* xw1  = (const float*)d_in[11];
    const float* dtw1 = (const float*)d_in[12];
    const float* dtb1 = (const float*)d_in[13];
    const float* Al1  = (const float*)d_in[14];
    const float* Dv1  = (const float*)d_in[15];
    const float* g1   = (const float*)d_in[16];
    const float* be1  = (const float*)d_in[17];
    const float* xw2  = (const float*)d_in[18];
    const float* dtw2 = (const float*)d_in[19];
    const float* dtb2 = (const float*)d_in[20];
    const float* Al2  = (const float*)d_in[21];
    const float* Dv2  = (const float*)d_in[22];
    const float* g2   = (const float*)d_in[23];
    const float* be2  = (const float*)d_in[24];
    const float* xw3  = (const float*)d_in[25];
    const float* dtw3 = (const float*)d_in[26];
    const float* dtb3 = (const float*)d_in[27];
    const float* Al3  = (const float*)d_in[28];
    const float* Dv3  = (const float*)d_in[29];
    const float* g3   = (const float*)d_in[30];
    const float* be3  = (const float*)d_in[31];

    static float *p_xz = nullptr, *p_f1, *p_f2, *p_f3,
                 *p_xd1f, *p_xd1b, *p_xd2, *p_xd3,
                 *p_yf1, *p_yb1, *p_yf2, *p_yb2, *p_yf3, *p_yb3,
                 *p_y3, *p_y2, *p_y1m;
    if (!p_xz) {
        cudaGetSymbolAddress((void**)&p_xz,  g_xz);
        cudaGetSymbolAddress((void**)&p_f1,  g_f1);
        cudaGetSymbolAddress((void**)&p_f2,  g_f2);
        cudaGetSymbolAddress((void**)&p_f3,  g_f3);
        cudaGetSymbolAddress((void**)&p_xd1f, g_xd1f);
        cudaGetSymbolAddress((void**)&p_xd1b, g_xd1b);
        cudaGetSymbolAddress((void**)&p_xd2, g_xd2);
        cudaGetSymbolAddress((void**)&p_xd3, g_xd3);
        cudaGetSymbolAddress((void**)&p_yf1, g_yf1);
        cudaGetSymbolAddress((void**)&p_yb1, g_yb1);
        cudaGetSymbolAddress((void**)&p_yf2, g_yf2);
        cudaGetSymbolAddress((void**)&p_yb2, g_yb2);
        cudaGetSymbolAddress((void**)&p_yf3, g_yf3);
        cudaGetSymbolAddress((void**)&p_yb3, g_yb3);
        cudaGetSymbolAddress((void**)&p_y3,  g_y3);
        cudaGetSymbolAddress((void**)&p_y2,  g_y2);
        cudaGetSymbolAddress((void**)&p_y1m, g_y1m);
    }

    // 1) in-proj: xz[b,l,512] = in_w @ input_f + in_b   (A is channel-first strided)
    sgemm_bias<<<dim3(512 / BN, 8192 / BM), 256>>>(
        input_f, 1, 1024, (long long)512 * 1024,
        in_w, in_b, p_xz, 8192, 512, 512, 0);

    // 2) c1: f1 = c1_w @ x (+b), x = xz[:, :256]
    sgemm_bias<<<dim3(256 / BN, 8192 / BM), 256>>>(
        p_xz, 512, 1, (long long)1024 * 512,
        c1_w, c1_b, p_f1, 8192, 256, 256, 0);

    // 3-4) strided convs
    conv2s2<<<dim3(32, 8), 256>>>(p_f1, c2_w, c2_b, p_f2, 32, 16);
    conv2s2<<<dim3(8, 8), 256>>>(p_f2, c3_w, c3_b, p_f3, 16, 8);

    // 5) xd projections (note: level-1 backward uses xw2 — reference quirk)
    xd_kernel<<<NB * L1V, 256>>>(p_f1, xw1, p_xd1f);
    xd_kernel<<<NB * L1V, 256>>>(p_f1, xw2, p_xd1b);
    xd_kernel<<<NB * L2V, 256>>>(p_f2, xw2, p_xd2);
    xd_kernel<<<NB * L3V, 256>>>(p_f3, xw3, p_xd3);

    // 6) all 6 scans in one launch
    scan_kernel<<<384, 32>>>(dtw1, dtb1, Al1, Dv1,
                             dtw2, dtb2, Al2, Dv2,
                             dtw3, dtb3, Al3, Dv3);

    // 7) y3 = LN(yf3;3) + LN(yb3;3)
    ln_kernel<<<NB * L3V, 256>>>(p_yf3, p_yb3, g3, be3, g3, be3,
                                 nullptr, 0, 0, nullptr, p_y3, L3V);
    // 8) y2 = LN(yf2;2) + LN(yb2;2) + up2(y3)
    ln_kernel<<<NB * L2V, 256>>>(p_yf2, p_yb2, g2, be2, g2, be2,
                                 p_y3, 8, 16, nullptr, p_y2, L2V);
    // 9) y1m = (LN(yf1;1) + LN(yb1;2) + up2(y2)) * silu(z)   (bwd LN uses set-2 params)
    ln_kernel<<<NB * L1V, 256>>>(p_yf1, p_yb1, g1, be1, g2, be2,
                                 p_y2, 16, 32, p_xz, p_y1m, L1V);

    // 10) out-proj to CHW output
    sgemm_bias<<<dim3(512 / BN, 8192 / BM), 256>>>(
        p_y1m, 256, 1, (long long)1024 * 256,
        out_w, out_b, (float*)d_out, 8192, 512, 256, 1);
}

// round 2
// speedup vs baseline: 1.3748x; 1.3748x over previous
#include <cuda_runtime.h>
#include <math.h>

#define NB 8
#define NC 256
#define L1V 1024
#define L2V 256
#define L3V 64

// ---------------- scratch ----------------
__device__ float g_xz [NB*L1V*512];
__device__ float g_f1 [NB*L1V*NC];
__device__ float g_f2 [NB*L2V*NC];
__device__ float g_f3 [NB*L3V*NC];
__device__ float g_w2t[256*1024];
__device__ float g_w3t[256*1024];
__device__ float g_xd1f[NB*L1V*40];
__device__ float g_xd1b[NB*L1V*40];
__device__ float g_xd2 [NB*L2V*40];
__device__ float g_xd3 [NB*L3V*40];
__device__ float g_yf1[NB*L1V*NC];
__device__ float g_yb1[NB*L1V*NC];
__device__ float g_yf2[NB*L2V*NC];
__device__ float g_yb2[NB*L2V*NC];
__device__ float g_yf3[NB*L3V*NC];
__device__ float g_yb3[NB*L3V*NC];
__device__ float g_y3 [NB*L3V*NC];
__device__ float g_y2 [NB*L2V*NC];
__device__ float g_y1m[NB*L1V*NC];

// ============================================================================
// GEMM: C[m][n] = sum_k A[m][k]*W[n][k] (+bias)
// AMODE 0: A row-major, row stride a_rs
// AMODE 1: A chw (in-proj): addr = (m>>10)*a_bstride + (m&1023) + k*1024
// AMODE 2: A im2col from channel-last conv input (Win,Wout), K = q*256+c
// OMODE 0: C[m*N+n] = acc + bias[n]
// OMODE 1: atomicAdd(C[m*256+n], acc)           (split-K convs)
// OMODE 2: CHW store: C[(n>>10)*512*1024 + m*1024 + (n&1023)] = acc + bias[m]
// ============================================================================
#define BM 128
#define BN 128
#define BK 16

template<int AMODE, int OMODE>
__global__ __launch_bounds__(256, 2) void gemm_k(
    const float* __restrict__ A, int a_rs, long long a_bstride,
    int Win, int Wout,
    const float* __restrict__ W, int w_rs,
    const float* __restrict__ bias,
    float* __restrict__ C, int N, int Kc)
{
    __shared__ float As[2][BK][BM];
    __shared__ float Ws[2][BK][BN];
    int tid = threadIdx.x;
    int bm = blockIdx.y * BM;
    int bn = blockIdx.x * BN;
    int kstart = blockIdx.z * Kc;

    long long a_base = 0;
    int a_q_base[4];
    if (AMODE == 0) {
        int m = bm + (tid >> 1);
        a_base = (long long)m * a_rs;
    } else if (AMODE == 1) {
        int m = bm + (tid & 127);
        a_base = (long long)(m >> 10) * a_bstride + (m & 1023);
    } else {
        int m = bm + (tid >> 1);
        int PP = Wout * Wout;
        int b = m / PP;
        int p = m - b * PP;
        int i = p / Wout;
        int j = p - i * Wout;
#pragma unroll
        for (int q = 0; q < 4; q++) {
            int dy = q >> 1, dx = q & 1;
            a_q_base[q] = ((b * Win + 2 * i + dy) * Win + 2 * j + dx) * 256;
        }
    }
    long long w_base = (long long)(bn + (tid >> 1)) * w_rs;

    float ra[8], rw[8];

    auto loadA = [&](int k0) {
        if (AMODE == 1) {
            int kk0 = (tid >> 7) * 8;
#pragma unroll
            for (int i = 0; i < 8; i++)
                ra[i] = A[a_base + (long long)(k0 + kk0 + i) * 1024];
        } else if (AMODE == 0) {
            int k = k0 + (tid & 1) * 8;
            float4 v0 = *reinterpret_cast<const float4*>(A + a_base + k);
            float4 v1 = *reinterpret_cast<const float4*>(A + a_base + k + 4);
            ra[0]=v0.x; ra[1]=v0.y; ra[2]=v0.z; ra[3]=v0.w;
            ra[4]=v1.x; ra[5]=v1.y; ra[6]=v1.z; ra[7]=v1.w;
        } else {
            int k = k0 + (tid & 1) * 8;
            int q = k >> 8, c = k & 255;
            float4 v0 = *reinterpret_cast<const float4*>(A + a_q_base[q] + c);
            float4 v1 = *reinterpret_cast<const float4*>(A + a_q_base[q] + c + 4);
            ra[0]=v0.x; ra[1]=v0.y; ra[2]=v0.z; ra[3]=v0.w;
            ra[4]=v1.x; ra[5]=v1.y; ra[6]=v1.z; ra[7]=v1.w;
        }
    };
    auto loadW = [&](int k0) {
        int k = k0 + (tid & 1) * 8;
        float4 v0 = *reinterpret_cast<const float4*>(W + w_base + k);
        float4 v1 = *reinterpret_cast<const float4*>(W + w_base + k + 4);
        rw[0]=v0.x; rw[1]=v0.y; rw[2]=v0.z; rw[3]=v0.w;
        rw[4]=v1.x; rw[5]=v1.y; rw[6]=v1.z; rw[7]=v1.w;
    };
    auto stsA = [&](int buf) {
        if (AMODE == 1) {
            int m = tid & 127, kk0 = (tid >> 7) * 8;
#pragma unroll
            for (int i = 0; i < 8; i++) As[buf][kk0 + i][m] = ra[i];
        } else {
            int m = tid >> 1, kk0 = (tid & 1) * 8;
#pragma unroll
            for (int i = 0; i < 8; i++) As[buf][kk0 + i][m] = ra[i];
        }
    };
    auto stsW = [&](int buf) {
        int n = tid >> 1, kk0 = (tid & 1) * 8;
#pragma unroll
        for (int i = 0; i < 8; i++) Ws[buf][kk0 + i][n] = rw[i];
    };

    int tx = tid & 15, ty = tid >> 4;
    float acc[8][8];
#pragma unroll
    for (int i = 0; i < 8; i++)
#pragma unroll
        for (int j = 0; j < 8; j++) acc[i][j] = 0.f;

    loadA(kstart); loadW(kstart);
    stsA(0); stsW(0);
    __syncthreads();

    int ktiles = Kc / BK;
    for (int t = 0; t < ktiles; t++) {
        int buf = t & 1;
        if (t + 1 < ktiles) { loadA(kstart + (t + 1) * BK); loadW(kstart + (t + 1) * BK); }
#pragma unroll
        for (int kk = 0; kk < BK; kk++) {
            float av[8], bv[8];
            float4 a0 = *reinterpret_cast<const float4*>(&As[buf][kk][ty * 8]);
            float4 a1 = *reinterpret_cast<const float4*>(&As[buf][kk][ty * 8 + 4]);
            float4 b0 = *reinterpret_cast<const float4*>(&Ws[buf][kk][tx * 8]);
            float4 b1 = *reinterpret_cast<const float4*>(&Ws[buf][kk][tx * 8 + 4]);
            av[0]=a0.x; av[1]=a0.y; av[2]=a0.z; av[3]=a0.w;
            av[4]=a1.x; av[5]=a1.y; av[6]=a1.z; av[7]=a1.w;
            bv[0]=b0.x; bv[1]=b0.y; bv[2]=b0.z; bv[3]=b0.w;
            bv[4]=b1.x; bv[5]=b1.y; bv[6]=b1.z; bv[7]=b1.w;
#pragma unroll
            for (int i = 0; i < 8; i++)
#pragma unroll
                for (int j = 0; j < 8; j++) acc[i][j] = fmaf(av[i], bv[j], acc[i][j]);
        }
        if (t + 1 < ktiles) { stsA(buf ^ 1); stsW(buf ^ 1); __syncthreads(); }
    }

    if (OMODE == 0) {
#pragma unroll
        for (int i = 0; i < 8; i++) {
            int m = bm + ty * 8 + i;
            int n0 = bn + tx * 8;
            float4 o0, o1;
            o0.x = acc[i][0] + bias[n0 + 0]; o0.y = acc[i][1] + bias[n0 + 1];
            o0.z = acc[i][2] + bias[n0 + 2]; o0.w = acc[i][3] + bias[n0 + 3];
            o1.x = acc[i][4] + bias[n0 + 4]; o1.y = acc[i][5] + bias[n0 + 5];
            o1.z = acc[i][6] + bias[n0 + 6]; o1.w = acc[i][7] + bias[n0 + 7];
            *reinterpret_cast<float4*>(C + (long long)m * N + n0)     = o0;
            *reinterpret_cast<float4*>(C + (long long)m * N + n0 + 4) = o1;
        }
    } else if (OMODE == 1) {
#pragma unroll
        for (int i = 0; i < 8; i++) {
            long long base = (long long)(bm + ty * 8 + i) * 256 + bn + tx * 8;
#pragma unroll
            for (int j = 0; j < 8; j++) atomicAdd(C + base + j, acc[i][j]);
        }
    } else {
        int b = bn >> 10;
        int nloc = (bn & 1023) + tx * 8;
#pragma unroll
        for (int i = 0; i < 8; i++) {
            int m = bm + ty * 8 + i;
            float bb = bias[m];
            long long base = (long long)b * 512 * 1024 + (long long)m * 1024 + nloc;
            float4 o0, o1;
            o0.x = acc[i][0] + bb; o0.y = acc[i][1] + bb; o0.z = acc[i][2] + bb; o0.w = acc[i][3] + bb;
            o1.x = acc[i][4] + bb; o1.y = acc[i][5] + bb; o1.z = acc[i][6] + bb; o1.w = acc[i][7] + bb;
            *reinterpret_cast<float4*>(C + base)     = o0;
            *reinterpret_cast<float4*>(C + base + 4) = o1;
        }
    }
}

// ---------------- conv weight transpose: [o][c][q] -> [o][q][c] ----------------
__global__ __launch_bounds__(256) void wtrans(const float* __restrict__ w, float* __restrict__ wt)
{
    int o = blockIdx.x, c = threadIdx.x;
    float4 v = *reinterpret_cast<const float4*>(w + (long long)o * 1024 + c * 4);
    wt[(long long)o * 1024 + 0   + c] = v.x;
    wt[(long long)o * 1024 + 256 + c] = v.y;
    wt[(long long)o * 1024 + 512 + c] = v.z;
    wt[(long long)o * 1024 + 768 + c] = v.w;
}

// ---------------- fill rows with bias (pre-split-K init) ----------------
__global__ __launch_bounds__(256) void fill_bias(float* __restrict__ out, const float* __restrict__ bias)
{
    out[(long long)blockIdx.x * 256 + threadIdx.x] = bias[threadIdx.x];
}

// ---------------- xd: one or two 40-dim projections of f rows ----------------
__global__ __launch_bounds__(256) void xd2_kernel(
    const float* __restrict__ f,
    const float* __restrict__ xwA, const float* __restrict__ xwB,
    float* __restrict__ xdA, float* __restrict__ xdB)
{
    __shared__ float row[256];
    long long bl = blockIdx.x;
    row[threadIdx.x] = f[bl * 256 + threadIdx.x];
    __syncthreads();
    int warp = threadIdx.x >> 5, lane = threadIdx.x & 31;
    int nk = xwB ? 10 : 5;
    for (int kk = 0; kk < nk; kk++) {
        int k = warp * 5 + (kk < 5 ? kk : kk - 5);
        const float* xw = (kk < 5) ? xwA : xwB;
        float s = 0.f;
#pragma unroll
        for (int e = 0; e < 8; e++)
            s = fmaf(row[lane + 32 * e], xw[k * 256 + lane + 32 * e], s);
#pragma unroll
        for (int off = 16; off; off >>= 1) s += __shfl_down_sync(0xffffffffu, s, off);
        if (lane == 0) ((kk < 5) ? xdA : xdB)[bl * 40 + k] = s;
    }
}

// ---------------- selective scan ----------------
__global__ __launch_bounds__(32) void scan_kernel(
    const float* __restrict__ dtw1, const float* __restrict__ dtb1,
    const float* __restrict__ Al1,  const float* __restrict__ Dv1,
    const float* __restrict__ dtw2, const float* __restrict__ dtb2,
    const float* __restrict__ Al2,  const float* __restrict__ Dv2,
    const float* __restrict__ dtw3, const float* __restrict__ dtb3,
    const float* __restrict__ Al3,  const float* __restrict__ Dv3)
{
    int bx   = blockIdx.x;
    int lvl  = bx >> 7;
    int r    = bx & 127;
    int dir  = r >> 6;
    int b    = (r >> 3) & 7;
    int lane = threadIdx.x;
    int d    = (r & 7) * 32 + lane;

    const float *f, *xd, *dtw, *dtb, *Al, *Dv;
    float* y;
    int L;
    if (lvl == 0) {
        L = L1V; f = g_f1;
        xd = dir ? g_xd1b : g_xd1f;
        y  = dir ? g_yb1  : g_yf1;
        if (dir) { dtw = dtw2; dtb = dtb2; Al = Al2; Dv = Dv2; }
        else     { dtw = dtw1; dtb = dtb1; Al = Al1; Dv = Dv1; }
    } else if (lvl == 1) {
        L = L2V; f = g_f2; xd = g_xd2;
        y = dir ? g_yb2 : g_yf2;
        dtw = dtw2; dtb = dtb2; Al = Al2; Dv = Dv2;
    } else {
        L = L3V; f = g_f3; xd = g_xd3;
        y = dir ? g_yb3 : g_yf3;
        dtw = dtw3; dtb = dtb3; Al = Al3; Dv = Dv3;
    }
    f  += (long long)b * L * 256;
    xd += (long long)b * L * 40;
    y  += (long long)b * L * 256;

    float w[8];
#pragma unroll
    for (int rr = 0; rr < 8; rr++) w[rr] = dtw[d * 8 + rr];
    float bdt = dtb[d];
    float Areg[16];
    bool pl = true;
#pragma unroll
    for (int n = 0; n < 16; n++) {
        Areg[n] = -expf(Al[d * 16 + n]);
        pl = pl && (fabsf(Areg[n] + (float)(n + 1)) < 1e-3f * (n + 1));
    }
    float Dvv = Dv[d];
    float h[16];
#pragma unroll
    for (int n = 0; n < 16; n++) h[n] = 0.f;

    __shared__ __align__(16) float sxd[8][40];

    for (int s0 = 0; s0 < L; s0 += 8) {
        __syncwarp();
        for (int t = lane; t < 80; t += 32) {
            int ss = t / 10, kk = t - ss * 10;
            int l = dir ? (L - 1 - (s0 + ss)) : (s0 + ss);
            reinterpret_cast<float4*>(&sxd[ss][0])[kk] =
                reinterpret_cast<const float4*>(xd + (long long)l * 40)[kk];
        }
        float xa[8];
#pragma unroll
        for (int ss = 0; ss < 8; ss++) {
            int l = dir ? (L - 1 - (s0 + ss)) : (s0 + ss);
            xa[ss] = f[(long long)l * 256 + d];
        }
        __syncwarp();
#pragma unroll
        for (int ss = 0; ss < 8; ss++) {
            float4 t0 = *reinterpret_cast<const float4*>(&sxd[ss][0]);
            float4 t1 = *reinterpret_cast<const float4*>(&sxd[ss][4]);
            float delta = bdt;
            delta = fmaf(t0.x, w[0], delta); delta = fmaf(t0.y, w[1], delta);
            delta = fmaf(t0.z, w[2], delta); delta = fmaf(t0.w, w[3], delta);
            delta = fmaf(t1.x, w[4], delta); delta = fmaf(t1.y, w[5], delta);
            delta = fmaf(t1.z, w[6], delta); delta = fmaf(t1.w, w[7], delta);
            // softplus
            float e = __expf(-fabsf(delta));
            delta = fmaxf(delta, 0.f) + __logf(1.f + e);

            float dA[16];
            if (pl) {
                float q  = __expf(-delta);
                float q2 = q * q;
                float q4 = q2 * q2;
                float q8 = q4 * q4;
                dA[0] = q;        dA[1] = q2;       dA[2] = q2 * q;   dA[3] = q4;
                dA[4] = q4 * q;   dA[5] = q4 * q2;  dA[6] = q4 * dA[2]; dA[7] = q8;
                dA[8] = q8 * q;   dA[9] = q8 * q2;  dA[10] = q8 * dA[2]; dA[11] = q8 * q4;
                dA[12] = q8 * dA[4]; dA[13] = q8 * dA[5]; dA[14] = q8 * dA[6]; dA[15] = q8 * q8;
            } else {
#pragma unroll
                for (int n = 0; n < 16; n++) dA[n] = __expf(delta * Areg[n]);
            }

            float dxv = delta * xa[ss];
            float4 B0 = *reinterpret_cast<const float4*>(&sxd[ss][8]);
            float4 B1 = *reinterpret_cast<const float4*>(&sxd[ss][12]);
            float4 B2 = *reinterpret_cast<const float4*>(&sxd[ss][16]);
            float4 B3 = *reinterpret_cast<const float4*>(&sxd[ss][20]);
            float4 C0 = *reinterpret_cast<const float4*>(&sxd[ss][24]);
            float4 C1 = *reinterpret_cast<const float4*>(&sxd[ss][28]);
            float4 C2 = *reinterpret_cast<const float4*>(&sxd[ss][32]);
            float4 C3 = *reinterpret_cast<const float4*>(&sxd[ss][36]);
            float Bv[16] = {B0.x,B0.y,B0.z,B0.w,B1.x,B1.y,B1.z,B1.w,
                            B2.x,B2.y,B2.z,B2.w,B3.x,B3.y,B3.z,B3.w};
            float Cv[16] = {C0.x,C0.y,C0.z,C0.w,C1.x,C1.y,C1.z,C1.w,
                            C2.x,C2.y,C2.z,C2.w,C3.x,C3.y,C3.z,C3.w};
            float yv = 0.f;
#pragma unroll
            for (int n = 0; n < 16; n++) {
                h[n] = fmaf(h[n], dA[n], dxv * Bv[n]);
                yv = fmaf(h[n], Cv[n], yv);
            }
            yv = fmaf(xa[ss], Dvv, yv);
            int l = dir ? (L - 1 - (s0 + ss)) : (s0 + ss);
            y[(long long)l * 256 + d] = yv;
        }
    }
}

// ---------------- double LayerNorm + upsample-add + silu gate ----------------
__global__ __launch_bounds__(256) void ln_kernel(
    const float* __restrict__ yf, const float* __restrict__ yb,
    const float* __restrict__ gf, const float* __restrict__ bef,
    const float* __restrict__ gb, const float* __restrict__ beb,
    const float* __restrict__ up, int upSrcW, int dstW,
    const float* __restrict__ z, float* __restrict__ out, int L)
{
    __shared__ float red[4][8];
    int bl = blockIdx.x;
    int b  = bl / L;
    int l  = bl - b * L;
    int c  = threadIdx.x;
    long long idx = (long long)bl * 256 + c;
    float vf = yf[idx], vb = yb[idx];

    float s0 = vf, s1 = vf * vf, s2 = vb, s3 = vb * vb;
#pragma unroll
    for (int off = 16; off; off >>= 1) {
        s0 += __shfl_down_sync(0xffffffffu, s0, off);
        s1 += __shfl_down_sync(0xffffffffu, s1, off);
        s2 += __shfl_down_sync(0xffffffffu, s2, off);
        s3 += __shfl_down_sync(0xffffffffu, s3, off);
    }
    int warp = c >> 5, lane = c & 31;
    if (lane == 0) { red[0][warp] = s0; red[1][warp] = s1; red[2][warp] = s2; red[3][warp] = s3; }
    __syncthreads();
    float sf = 0.f, sf2 = 0.f, sb = 0.f, sb2 = 0.f;
#pragma unroll
    for (int wv = 0; wv < 8; wv++) {
        sf += red[0][wv]; sf2 += red[1][wv]; sb += red[2][wv]; sb2 += red[3][wv];
    }
    const float inv = 1.f / 256.f;
    float muf = sf * inv, varf = sf2 * inv - muf * muf;
    float mub = sb * inv, varb = sb2 * inv - mub * mub;
    float nf = (vf - muf) * rsqrtf(varf + 1e-5f) * gf[c] + bef[c];
    float nb = (vb - mub) * rsqrtf(varb + 1e-5f) * gb[c] + beb[c];
    float v = nf + nb;
    if (up) {
        int i = l / dstW, j = l - (l / dstW) * dstW;
        v += up[((long long)b * upSrcW * upSrcW + (i >> 1) * upSrcW + (j >> 1)) * 256 + c];
    }
    if (z) {
        float zz = z[(long long)bl * 512 + 256 + c];
        v *= zz / (1.f + __expf(-zz));
    }
    out[idx] = v;
}

// ---------------- launch ----------------
extern "C" void kernel_launch(void* const* d_in, const int* in_sizes, int n_in,
                              void* d_out, int out_size)
{
    const float* input_f = (const float*)d_in[0];
    const float* in_w  = (const float*)d_in[1];
    const float* in_b  = (const float*)d_in[2];
    const float* c1_w  = (const float*)d_in[3];
    const float* c1_b  = (const float*)d_in[4];
    const float* c2_w  = (const float*)d_in[5];
    const float* c2_b  = (const float*)d_in[6];
    const float* c3_w  = (const float*)d_in[7];
    const float* c3_b  = (const float*)d_in[8];
    const float* out_w = (const float*)d_in[9];
    const float* out_b = (const float*)d_in[10];
    const float* xw1  = (const float*)d_in[11];
    const float* dtw1 = (const float*)d_in[12];
    const float* dtb1 = (const float*)d_in[13];
    const float* Al1  = (const float*)d_in[14];
    const float* Dv1  = (const float*)d_in[15];
    const float* g1   = (const float*)d_in[16];
    const float* be1  = (const float*)d_in[17];
    const float* xw2  = (const float*)d_in[18];
    const float* dtw2 = (const float*)d_in[19];
    const float* dtb2 = (const float*)d_in[20];
    const float* Al2  = (const float*)d_in[21];
    const float* Dv2  = (const float*)d_in[22];
    const float* g2   = (const float*)d_in[23];
    const float* be2  = (const float*)d_in[24];
    const float* xw3  = (const float*)d_in[25];
    const float* dtw3 = (const float*)d_in[26];
    const float* dtb3 = (const float*)d_in[27];
    const float* Al3  = (const float*)d_in[28];
    const float* Dv3  = (const float*)d_in[29];
    const float* g3   = (const float*)d_in[30];
    const float* be3  = (const float*)d_in[31];

    static float *p_xz = nullptr, *p_f1, *p_f2, *p_f3, *p_w2t, *p_w3t,
                 *p_xd1f, *p_xd1b, *p_xd2, *p_xd3,
                 *p_yf1, *p_yb1, *p_yf2, *p_yb2, *p_yf3, *p_yb3,
                 *p_y3, *p_y2, *p_y1m;
    if (!p_xz) {
        cudaGetSymbolAddress((void**)&p_xz,  g_xz);
        cudaGetSymbolAddress((void**)&p_f1,  g_f1);
        cudaGetSymbolAddress((void**)&p_f2,  g_f2);
        cudaGetSymbolAddress((void**)&p_f3,  g_f3);
        cudaGetSymbolAddress((void**)&p_w2t, g_w2t);
        cudaGetSymbolAddress((void**)&p_w3t, g_w3t);
        cudaGetSymbolAddress((void**)&p_xd1f, g_xd1f);
        cudaGetSymbolAddress((void**)&p_xd1b, g_xd1b);
        cudaGetSymbolAddress((void**)&p_xd2, g_xd2);
        cudaGetSymbolAddress((void**)&p_xd3, g_xd3);
        cudaGetSymbolAddress((void**)&p_yf1, g_yf1);
        cudaGetSymbolAddress((void**)&p_yb1, g_yb1);
        cudaGetSymbolAddress((void**)&p_yf2, g_yf2);
        cudaGetSymbolAddress((void**)&p_yb2, g_yb2);
        cudaGetSymbolAddress((void**)&p_yf3, g_yf3);
        cudaGetSymbolAddress((void**)&p_yb3, g_yb3);
        cudaGetSymbolAddress((void**)&p_y3,  g_y3);
        cudaGetSymbolAddress((void**)&p_y2,  g_y2);
        cudaGetSymbolAddress((void**)&p_y1m, g_y1m);
    }

    // conv weight transposes (independent, tiny)
    wtrans<<<256, 256>>>(c2_w, p_w2t);
    wtrans<<<256, 256>>>(c3_w, p_w3t);

    // 1) in-proj: xz[bl,512], A chw
    gemm_k<1, 0><<<dim3(4, 64, 1), 256>>>(
        input_f, 0, (long long)512 * 1024, 0, 0,
        in_w, 512, in_b, p_xz, 512, 512);

    // 2) c1: f1[bl,256] from xz[:, :256]
    gemm_k<0, 0><<<dim3(2, 64, 1), 256>>>(
        p_xz, 512, 0, 0, 0,
        c1_w, 256, c1_b, p_f1, 256, 256);

    // 3) conv1 (32->16): split-K GEMM, M=2048, K=1024
    fill_bias<<<NB * L2V, 256>>>(p_f2, c2_b);
    gemm_k<2, 1><<<dim3(2, 16, 8), 256>>>(
        p_f1, 0, 0, 32, 16,
        p_w2t, 1024, nullptr, p_f2, 256, 128);

    // 4) conv2 (16->8): split-K GEMM, M=512, K=1024
    fill_bias<<<NB * L3V, 256>>>(p_f3, c3_b);
    gemm_k<2, 1><<<dim3(2, 4, 16), 256>>>(
        p_f2, 0, 0, 16, 8,
        p_w3t, 1024, nullptr, p_f3, 256, 64);

    // 5) xd projections (level-1 backward uses xw2 — reference quirk)
    xd2_kernel<<<NB * L1V, 256>>>(p_f1, xw1, xw2, p_xd1f, p_xd1b);
    xd2_kernel<<<NB * L2V, 256>>>(p_f2, xw2, nullptr, p_xd2, nullptr);
    xd2_kernel<<<NB * L3V, 256>>>(p_f3, xw3, nullptr, p_xd3, nullptr);

    // 6) all 6 scans
    scan_kernel<<<384, 32>>>(dtw1, dtb1, Al1, Dv1,
                             dtw2, dtb2, Al2, Dv2,
                             dtw3, dtb3, Al3, Dv3);

    // 7-9) layernorm / upsample / gate chain
    ln_kernel<<<NB * L3V, 256>>>(p_yf3, p_yb3, g3, be3, g3, be3,
                                 nullptr, 0, 0, nullptr, p_y3, L3V);
    ln_kernel<<<NB * L2V, 256>>>(p_yf2, p_yb2, g2, be2, g2, be2,
                                 p_y3, 8, 16, nullptr, p_y2, L2V);
    ln_kernel<<<NB * L1V, 256>>>(p_yf1, p_yb1, g1, be1, g2, be2,
                                 p_y2, 16, 32, p_xz, p_y1m, L1V);

    // 10) out-proj, roles swapped: M=512 channels, N=8192 bl, coalesced CHW store
    gemm_k<0, 2><<<dim3(64, 4, 1), 256>>>(
        out_w, 256, 0, 0, 0,
        p_y1m, 256, out_b, (float*)d_out, 8192, 256);
}

// round 5
// speedup vs baseline: 1.4450x; 1.0511x over previous
#include <cuda_runtime.h>
#include <math.h>

#define NB 8
#define NC 256
#define L1V 1024
#define L2V 256
#define L3V 64

// ---------------- scratch ----------------
__device__ float g_xz [NB*L1V*512];
__device__ float g_f1 [NB*L1V*NC];
__device__ float g_f2 [NB*L2V*NC];
__device__ float g_f3 [NB*L3V*NC];
__device__ float g_w2t[256*1024];
__device__ float g_w3t[256*1024];
__device__ float g_xd1f[NB*L1V*40];
__device__ float g_xd1b[NB*L1V*40];
__device__ float g_xd2 [NB*L2V*40];
__device__ float g_xd3 [NB*L3V*40];
__device__ float g_q1f[NB*L1V*NC], g_dx1f[NB*L1V*NC];
__device__ float g_q1b[NB*L1V*NC], g_dx1b[NB*L1V*NC];
__device__ float g_q2 [NB*L2V*NC], g_dx2 [NB*L2V*NC];
__device__ float g_q3 [NB*L3V*NC], g_dx3 [NB*L3V*NC];
__device__ float g_yf1[NB*L1V*NC];
__device__ float g_yb1[NB*L1V*NC];
__device__ float g_yf2[NB*L2V*NC];
__device__ float g_yb2[NB*L2V*NC];
__device__ float g_yf3[NB*L3V*NC];
__device__ float g_yb3[NB*L3V*NC];
__device__ float g_y3 [NB*L3V*NC];
__device__ float g_y2 [NB*L2V*NC];
__device__ float g_y1m[NB*L1V*NC];
// segmented-scan carries: lvl1 3 segs, lvl2 1 seg
__device__ float g_hend1[2*8*3*16*256];
__device__ float g_qtot1[2*8*3*256];
__device__ float g_hend2[2*8*16*256];
__device__ float g_qtot2[2*8*256];

// ---------------- packed f32x2 helpers ----------------
__device__ __forceinline__ unsigned long long f2pack(float lo, float hi) {
    unsigned long long r;
    asm("mov.b64 %0, {%1,%2};" : "=l"(r) : "f"(lo), "f"(hi));
    return r;
}
__device__ __forceinline__ void f2unpack(unsigned long long v, float& lo, float& hi) {
    asm("mov.b64 {%0,%1}, %2;" : "=f"(lo), "=f"(hi) : "l"(v));
}
__device__ __forceinline__ unsigned long long ffma2(unsigned long long a, unsigned long long b, unsigned long long c) {
    unsigned long long d;
    asm("fma.rn.f32x2 %0, %1, %2, %3;" : "=l"(d) : "l"(a), "l"(b), "l"(c));
    return d;
}
__device__ __forceinline__ unsigned long long fmul2(unsigned long long a, unsigned long long b) {
    unsigned long long d;
    asm("mul.rn.f32x2 %0, %1, %2;" : "=l"(d) : "l"(a), "l"(b));
    return d;
}

// ============================================================================
// GEMM: C[m][n] = sum_k A[m][k]*W[n][k] (+bias)   tiles 64(m) x 128(n) x 16(k)
// AMODE 0: A row-major stride a_rs; AMODE 1: chw (k-strided); AMODE 2: im2col
// OMODE 0: C[m*N+n]+bias[n]; OMODE 1: atomicAdd; OMODE 2: CHW store +bias[m]
// ============================================================================
#define BM 64
#define BN 128
#define BK 16

template<int AMODE, int OMODE>
__global__ __launch_bounds__(256, 3) void gemm_k(
    const float* __restrict__ A, int a_rs, long long a_bstride,
    int Win, int Wout,
    const float* __restrict__ W, int w_rs,
    const float* __restrict__ bias,
    float* __restrict__ C, int N, int Kc)
{
    __shared__ float As[2][BK][BM];
    __shared__ float Ws[2][BK][BN];
    int tid = threadIdx.x;
    int bm = blockIdx.y * BM;
    int bn = blockIdx.x * BN;
    int kstart = blockIdx.z * Kc;

    long long a_base = 0;
    int a_q_base[4];
    if (AMODE == 0) {
        int m = bm + (tid >> 2);
        a_base = (long long)m * a_rs;
    } else if (AMODE == 1) {
        int m = bm + (tid & 63);
        a_base = (long long)(m >> 10) * a_bstride + (m & 1023);
    } else {
        int m = bm + (tid >> 2);
        int PP = Wout * Wout;
        int b = m / PP;
        int p = m - b * PP;
        int i = p / Wout;
        int j = p - i * Wout;
#pragma unroll
        for (int q = 0; q < 4; q++) {
            int dy = q >> 1, dx = q & 1;
            a_q_base[q] = ((b * Win + 2 * i + dy) * Win + 2 * j + dx) * 256;
        }
    }
    long long w_base = (long long)(bn + (tid >> 1)) * w_rs;

    float ra[4], rw[8];

    auto loadA = [&](int k0) {
        if (AMODE == 1) {
            int kk0 = (tid >> 6) * 4;
#pragma unroll
            for (int i = 0; i < 4; i++)
                ra[i] = A[a_base + (long long)(k0 + kk0 + i) * 1024];
        } else if (AMODE == 0) {
            int k = k0 + (tid & 3) * 4;
            float4 v = *reinterpret_cast<const float4*>(A + a_base + k);
            ra[0]=v.x; ra[1]=v.y; ra[2]=v.z; ra[3]=v.w;
        } else {
            int k = k0 + (tid & 3) * 4;
            int q = k >> 8, c = k & 255;
            float4 v = *reinterpret_cast<const float4*>(A + a_q_base[q] + c);
            ra[0]=v.x; ra[1]=v.y; ra[2]=v.z; ra[3]=v.w;
        }
    };
    auto loadW = [&](int k0) {
        int k = k0 + (tid & 1) * 8;
        float4 v0 = *reinterpret_cast<const float4*>(W + w_base + k);
        float4 v1 = *reinterpret_cast<const float4*>(W + w_base + k + 4);
        rw[0]=v0.x; rw[1]=v0.y; rw[2]=v0.z; rw[3]=v0.w;
        rw[4]=v1.x; rw[5]=v1.y; rw[6]=v1.z; rw[7]=v1.w;
    };
    auto stsA = [&](int buf) {
        if (AMODE == 1) {
            int m = tid & 63, kk0 = (tid >> 6) * 4;
#pragma unroll
            for (int i = 0; i < 4; i++) As[buf][kk0 + i][m] = ra[i];
        } else {
            int m = tid >> 2, kk0 = (tid & 3) * 4;
#pragma unroll
            for (int i = 0; i < 4; i++) As[buf][kk0 + i][m] = ra[i];
        }
    };
    auto stsW = [&](int buf) {
        int n = tid >> 1, kk0 = (tid & 1) * 8;
#pragma unroll
        for (int i = 0; i < 8; i++) Ws[buf][kk0 + i][n] = rw[i];
    };

    int tx = tid & 15, ty = tid >> 4;
    float acc[4][8];
#pragma unroll
    for (int i = 0; i < 4; i++)
#pragma unroll
        for (int j = 0; j < 8; j++) acc[i][j] = 0.f;

    loadA(kstart); loadW(kstart);
    stsA(0); stsW(0);
    __syncthreads();

    int ktiles = Kc / BK;
    for (int t = 0; t < ktiles; t++) {
        int buf = t & 1;
        if (t + 1 < ktiles) { loadA(kstart + (t + 1) * BK); loadW(kstart + (t + 1) * BK); }
#pragma unroll
        for (int kk = 0; kk < BK; kk++) {
            float av[4], bv[8];
            float4 a0 = *reinterpret_cast<const float4*>(&As[buf][kk][ty * 4]);
            float4 b0 = *reinterpret_cast<const float4*>(&Ws[buf][kk][tx * 8]);
            float4 b1 = *reinterpret_cast<const float4*>(&Ws[buf][kk][tx * 8 + 4]);
            av[0]=a0.x; av[1]=a0.y; av[2]=a0.z; av[3]=a0.w;
            bv[0]=b0.x; bv[1]=b0.y; bv[2]=b0.z; bv[3]=b0.w;
            bv[4]=b1.x; bv[5]=b1.y; bv[6]=b1.z; bv[7]=b1.w;
#pragma unroll
            for (int i = 0; i < 4; i++)
#pragma unroll
                for (int j = 0; j < 8; j++) acc[i][j] = fmaf(av[i], bv[j], acc[i][j]);
        }
        if (t + 1 < ktiles) { stsA(buf ^ 1); stsW(buf ^ 1); __syncthreads(); }
    }

    if (OMODE == 0) {
#pragma unroll
        for (int i = 0; i < 4; i++) {
            int m = bm + ty * 4 + i;
            int n0 = bn + tx * 8;
            float4 o0, o1;
            o0.x = acc[i][0] + bias[n0 + 0]; o0.y = acc[i][1] + bias[n0 + 1];
            o0.z = acc[i][2] + bias[n0 + 2]; o0.w = acc[i][3] + bias[n0 + 3];
            o1.x = acc[i][4] + bias[n0 + 4]; o1.y = acc[i][5] + bias[n0 + 5];
            o1.z = acc[i][6] + bias[n0 + 6]; o1.w = acc[i][7] + bias[n0 + 7];
            *reinterpret_cast<float4*>(C + (long long)m * N + n0)     = o0;
            *reinterpret_cast<float4*>(C + (long long)m * N + n0 + 4) = o1;
        }
    } else if (OMODE == 1) {
#pragma unroll
        for (int i = 0; i < 4; i++) {
            long long base = (long long)(bm + ty * 4 + i) * 256 + bn + tx * 8;
#pragma unroll
            for (int j = 0; j < 8; j++) atomicAdd(C + base + j, acc[i][j]);
        }
    } else {
        int b = bn >> 10;
        int nloc = (bn & 1023) + tx * 8;
#pragma unroll
        for (int i = 0; i < 4; i++) {
            int m = bm + ty * 4 + i;
            float bb = bias[m];
            long long base = (long long)b * 512 * 1024 + (long long)m * 1024 + nloc;
            float4 o0, o1;
            o0.x = acc[i][0] + bb; o0.y = acc[i][1] + bb; o0.z = acc[i][2] + bb; o0.w = acc[i][3] + bb;
            o1.x = acc[i][4] + bb; o1.y = acc[i][5] + bb; o1.z = acc[i][6] + bb; o1.w = acc[i][7] + bb;
            *reinterpret_cast<float4*>(C + base)     = o0;
            *reinterpret_cast<float4*>(C + base + 4) = o1;
        }
    }
}

// ---------------- conv weight transpose ----------------
__global__ __launch_bounds__(256) void wtrans(const float* __restrict__ w, float* __restrict__ wt)
{
    int o = blockIdx.x, c = threadIdx.x;
    float4 v = *reinterpret_cast<const float4*>(w + (long long)o * 1024 + c * 4);
    wt[(long long)o * 1024 + 0   + c] = v.x;
    wt[(long long)o * 1024 + 256 + c] = v.y;
    wt[(long long)o * 1024 + 512 + c] = v.z;
    wt[(long long)o * 1024 + 768 + c] = v.w;
}

__global__ __launch_bounds__(256) void fill_bias(float* __restrict__ out, const float* __restrict__ bias)
{
    out[(long long)blockIdx.x * 256 + threadIdx.x] = bias[threadIdx.x];
}

// ---------------- xd + delta/q/dxv precompute ----------------
__global__ __launch_bounds__(256) void xdq_kernel(
    const float* __restrict__ f,
    const float* __restrict__ xwA, const float* __restrict__ dtwA, const float* __restrict__ dtbA,
    const float* __restrict__ xwB, const float* __restrict__ dtwB, const float* __restrict__ dtbB,
    float* __restrict__ xdA, float* __restrict__ qA, float* __restrict__ dxA,
    float* __restrict__ xdB, float* __restrict__ qB, float* __restrict__ dxB)
{
    __shared__ float row[256];
    __shared__ float sdts[2][8];
    long long bl = blockIdx.x;
    int tid = threadIdx.x;
    row[tid] = f[bl * 256 + tid];
    __syncthreads();
    int warp = tid >> 5, lane = tid & 31;
    int nk = xwB ? 10 : 5;
    for (int kk = 0; kk < nk; kk++) {
        int set = (kk < 5) ? 0 : 1;
        int k = warp * 5 + (kk < 5 ? kk : kk - 5);
        const float* xw = set ? xwB : xwA;
        float s = 0.f;
#pragma unroll
        for (int e = 0; e < 8; e++)
            s = fmaf(row[lane + 32 * e], xw[k * 256 + lane + 32 * e], s);
#pragma unroll
        for (int off = 16; off; off >>= 1) s += __shfl_down_sync(0xffffffffu, s, off);
        if (lane == 0) {
            (set ? xdB : xdA)[bl * 40 + k] = s;
            if (k < 8) sdts[set][k] = s;
        }
    }
    __syncthreads();
    float xval = row[tid];
    {
        float acc = dtbA[tid];
#pragma unroll
        for (int r = 0; r < 8; r++) acc = fmaf(sdts[0][r], dtwA[tid * 8 + r], acc);
        float e = __expf(-fabsf(acc));
        float sp = fmaxf(acc, 0.f) + __logf(1.f + e);
        qA[bl * 256 + tid]  = __expf(-sp);
        dxA[bl * 256 + tid] = sp * xval;
    }
    if (xwB) {
        float acc = dtbB[tid];
#pragma unroll
        for (int r = 0; r < 8; r++) acc = fmaf(sdts[1][r], dtwB[tid * 8 + r], acc);
        float e = __expf(-fabsf(acc));
        float sp = fmaxf(acc, 0.f) + __logf(1.f + e);
        qB[bl * 256 + tid]  = __expf(-sp);
        dxB[bl * 256 + tid] = sp * xval;
    }
}

// ---------------- pass A: per-segment (h_end, carry) ----------------
// blocks: [0,384) lvl1 (segs 0..2), [384,512) lvl2 (seg 0)
__global__ __launch_bounds__(32) void scanA_kernel(
    const float* __restrict__ Al1, const float* __restrict__ Al2)
{
    int i = blockIdx.x;
    int dir, b, chunk, seg, L, seglen;
    const float *q, *dx, *xd, *Al;
    float *hend, *qtot;
    if (i < 384) {
        seg = i % 3; chunk = (i / 3) & 7; b = (i / 24) & 7; dir = i / 192;
        L = L1V; seglen = 256;
        q = dir ? g_q1b : g_q1f; dx = dir ? g_dx1b : g_dx1f;
        xd = dir ? g_xd1b : g_xd1f; Al = dir ? Al2 : Al1;
        int hidx = (dir * 8 + b) * 3 + seg;
        hend = g_hend1 + (long long)hidx * 16 * 256;
        qtot = g_qtot1 + (long long)hidx * 256;
    } else {
        int j = i - 384;
        seg = 0; chunk = j & 7; b = (j / 8) & 7; dir = j / 64;
        L = L2V; seglen = 128;
        q = g_q2; dx = g_dx2; xd = g_xd2; Al = Al2;
        int hidx = dir * 8 + b;
        hend = g_hend2 + (long long)hidx * 16 * 256;
        qtot = g_qtot2 + (long long)hidx * 256;
    }
    int lane = threadIdx.x;
    int d = chunk * 32 + lane;
    q  += (long long)b * L * 256;
    dx += (long long)b * L * 256;
    xd += (long long)b * L * 40;

    bool pl = true;
    float Areg[16];
#pragma unroll
    for (int n = 0; n < 16; n++) {
        Areg[n] = -expf(Al[d * 16 + n]);
        pl = pl && (fabsf(Areg[n] + (float)(n + 1)) < 1e-3f * (n + 1));
    }

    unsigned long long h8[8];
#pragma unroll
    for (int n = 0; n < 8; n++) h8[n] = 0ull;
    float carry = pl ? 1.f : 0.f;   // pl: prod q ; !pl: sum delta

    __shared__ __align__(16) float sxd[8][16];
    int t0 = seg * seglen;
    for (int tt = 0; tt < seglen; tt += 8) {
        __syncwarp();
        {
            int ss = lane >> 2, kk = lane & 3;
            int t = t0 + tt + ss;
            int l = dir ? (L - 1 - t) : t;
            *reinterpret_cast<float4*>(&sxd[ss][kk * 4]) =
                *reinterpret_cast<const float4*>(xd + (long long)l * 40 + 8 + kk * 4);
        }
        float q8[8], dx8[8];
#pragma unroll
        for (int ss = 0; ss < 8; ss++) {
            int t = t0 + tt + ss;
            int l = dir ? (L - 1 - t) : t;
            q8[ss]  = q [(long long)l * 256 + d];
            dx8[ss] = dx[(long long)l * 256 + d];
        }
        __syncwarp();
#pragma unroll
        for (int ss = 0; ss < 8; ss++) {
            float qq = q8[ss];
            unsigned long long dxv2 = f2pack(dx8[ss], dx8[ss]);
            if (pl) {
                float q2 = qq * qq;
                unsigned long long p  = f2pack(qq, q2);
                unsigned long long s2 = f2pack(q2, q2);
#pragma unroll
                for (int n = 0; n < 8; n++) {
                    unsigned long long B2 = *reinterpret_cast<const unsigned long long*>(&sxd[ss][2 * n]);
                    h8[n] = ffma2(h8[n], p, fmul2(dxv2, B2));
                    p = fmul2(p, s2);
                }
                carry *= qq;
            } else {
                float delta = -__logf(qq);
#pragma unroll
                for (int n = 0; n < 8; n++) {
                    unsigned long long dA2 = f2pack(__expf(delta * Areg[2 * n]),
                                                    __expf(delta * Areg[2 * n + 1]));
                    unsigned long long B2 = *reinterpret_cast<const unsigned long long*>(&sxd[ss][2 * n]);
                    h8[n] = ffma2(h8[n], dA2, fmul2(dxv2, B2));
                }
                carry += delta;
            }
        }
    }
#pragma unroll
    for (int n = 0; n < 8; n++) {
        float lo, hi;
        f2unpack(h8[n], lo, hi);
        hend[(2 * n)     * 256 + d] = lo;
        hend[(2 * n + 1) * 256 + d] = hi;
    }
    qtot[d] = carry;
}

// ---------------- pass B: combine prefix, produce y ----------------
// blocks: [0,512) lvl1, [512,768) lvl2, [768,896) lvl3
__global__ __launch_bounds__(32) void scanB_kernel(
    const float* __restrict__ Dv1, const float* __restrict__ Dv2, const float* __restrict__ Dv3,
    const float* __restrict__ Al1, const float* __restrict__ Al2, const float* __restrict__ Al3)
{
    int i = blockIdx.x;
    int dir, b, chunk, seg, L, seglen;
    const float *q, *dx, *xd, *Al, *Dv, *fsrc;
    float *y;
    const float *hend = nullptr, *qtot = nullptr;
    if (i < 512) {
        seg = i & 3; chunk = (i >> 2) & 7; b = (i >> 5) & 7; dir = i >> 8;
        L = L1V; seglen = 256;
        q = dir ? g_q1b : g_q1f; dx = dir ? g_dx1b : g_dx1f;
        xd = dir ? g_xd1b : g_xd1f;
        y  = dir ? g_yb1  : g_yf1;
        Al = dir ? Al2 : Al1; Dv = dir ? Dv2 : Dv1;
        fsrc = g_f1;
        int hb = (dir * 8 + b) * 3;
        hend = g_hend1 + (long long)hb * 16 * 256;
        qtot = g_qtot1 + (long long)hb * 256;
    } else if (i < 768) {
        int j = i - 512;
        seg = j & 1; chunk = (j >> 1) & 7; b = (j >> 4) & 7; dir = j >> 7;
        L = L2V; seglen = 128;
        q = g_q2; dx = g_dx2; xd = g_xd2;
        y = dir ? g_yb2 : g_yf2;
        Al = Al2; Dv = Dv2;
        fsrc = g_f2;
        int hb = dir * 8 + b;
        hend = g_hend2 + (long long)hb * 16 * 256;
        qtot = g_qtot2 + (long long)hb * 256;
    } else {
        int j = i - 768;
        seg = 0; chunk = j & 7; b = (j >> 3) & 7; dir = j >> 6;
        L = L3V; seglen = 64;
        q = g_q3; dx = g_dx3; xd = g_xd3;
        y = dir ? g_yb3 : g_yf3;
        Al = Al3; Dv = Dv3;
        fsrc = g_f3;
    }
    int lane = threadIdx.x;
    int d = chunk * 32 + lane;
    q    += (long long)b * L * 256;
    dx   += (long long)b * L * 256;
    xd   += (long long)b * L * 40;
    y    += (long long)b * L * 256;
    fsrc += (long long)b * L * 256;

    bool pl = true;
    float Areg[16];
#pragma unroll
    for (int n = 0; n < 16; n++) {
        Areg[n] = -expf(Al[d * 16 + n]);
        pl = pl && (fabsf(Areg[n] + (float)(n + 1)) < 1e-3f * (n + 1));
    }
    float Dvv = Dv[d];

    unsigned long long h8[8];
#pragma unroll
    for (int n = 0; n < 8; n++) h8[n] = 0ull;

    // prefix combine over earlier segments
    for (int s = 0; s < seg; s++) {
        float cr = qtot[s * 256 + d];
        const float* he = hend + (long long)s * 16 * 256;
        if (pl) {
            float Q2 = cr * cr;
            unsigned long long P  = f2pack(cr, Q2);
            unsigned long long S2 = f2pack(Q2, Q2);
#pragma unroll
            for (int n = 0; n < 8; n++) {
                unsigned long long hv = f2pack(he[(2 * n) * 256 + d], he[(2 * n + 1) * 256 + d]);
                h8[n] = ffma2(h8[n], P, hv);
                P = fmul2(P, S2);
            }
        } else {
#pragma unroll
            for (int n = 0; n < 8; n++) {
                unsigned long long P = f2pack(__expf(cr * Areg[2 * n]), __expf(cr * Areg[2 * n + 1]));
                unsigned long long hv = f2pack(he[(2 * n) * 256 + d], he[(2 * n + 1) * 256 + d]);
                h8[n] = ffma2(h8[n], P, hv);
            }
        }
    }

    __shared__ __align__(16) float sxd[8][32];
    int t0 = seg * seglen;
    for (int tt = 0; tt < seglen; tt += 8) {
        __syncwarp();
#pragma unroll
        for (int it = 0; it < 2; it++) {
            int idx = lane + it * 32;
            int ss = idx >> 3, kk = idx & 7;
            int t = t0 + tt + ss;
            int l = dir ? (L - 1 - t) : t;
            *reinterpret_cast<float4*>(&sxd[ss][kk * 4]) =
                *reinterpret_cast<const float4*>(xd + (long long)l * 40 + 8 + kk * 4);
        }
        float q8[8], dx8[8], xa8[8];
#pragma unroll
        for (int ss = 0; ss < 8; ss++) {
            int t = t0 + tt + ss;
            int l = dir ? (L - 1 - t) : t;
            q8[ss]  = q   [(long long)l * 256 + d];
            dx8[ss] = dx  [(long long)l * 256 + d];
            xa8[ss] = fsrc[(long long)l * 256 + d];
        }
        __syncwarp();
#pragma unroll
        for (int ss = 0; ss < 8; ss++) {
            float qq = q8[ss];
            unsigned long long dxv2 = f2pack(dx8[ss], dx8[ss]);
            unsigned long long acc = 0ull;
            if (pl) {
                float q2 = qq * qq;
                unsigned long long p  = f2pack(qq, q2);
                unsigned long long s2 = f2pack(q2, q2);
#pragma unroll
                for (int n = 0; n < 8; n++) {
                    unsigned long long B2 = *reinterpret_cast<const unsigned long long*>(&sxd[ss][2 * n]);
                    unsigned long long C2 = *reinterpret_cast<const unsigned long long*>(&sxd[ss][16 + 2 * n]);
                    h8[n] = ffma2(h8[n], p, fmul2(dxv2, B2));
                    acc = ffma2(h8[n], C2, acc);
                    p = fmul2(p, s2);
                }
            } else {
                float delta = -__logf(qq);
#pragma unroll
                for (int n = 0; n < 8; n++) {
                    unsigned long long dA2 = f2pack(__expf(delta * Areg[2 * n]),
                                                    __expf(delta * Areg[2 * n + 1]));
                    unsigned long long B2 = *reinterpret_cast<const unsigned long long*>(&sxd[ss][2 * n]);
                    unsigned long long C2 = *reinterpret_cast<const unsigned long long*>(&sxd[ss][16 + 2 * n]);
                    h8[n] = ffma2(h8[n], dA2, fmul2(dxv2, B2));
                    acc = ffma2(h8[n], C2, acc);
                }
            }
            float alo, ahi;
            f2unpack(acc, alo, ahi);
            float yv = alo + ahi + xa8[ss] * Dvv;
            int t = t0 + tt + ss;
            int l = dir ? (L - 1 - t) : t;
            y[(long long)l * 256 + d] = yv;
        }
    }
}

// ---------------- double LayerNorm + upsample-add + silu gate ----------------
__global__ __launch_bounds__(256) void ln_kernel(
    const float* __restrict__ yf, const float* __restrict__ yb,
    const float* __restrict__ gf, const float* __restrict__ bef,
    const float* __restrict__ gb, const float* __restrict__ beb,
    const float* __restrict__ up, int upSrcW, int dstW,
    const float* __restrict__ z, float* __restrict__ out, int L)
{
    __shared__ float red[4][8];
    int bl = blockIdx.x;
    int b  = bl / L;
    int l  = bl - b * L;
    int c  = threadIdx.x;
    long long idx = (long long)bl * 256 + c;
    float vf = yf[idx], vb = yb[idx];

    float s0 = vf, s1 = vf * vf, s2 = vb, s3 = vb * vb;
#pragma unroll
    for (int off = 16; off; off >>= 1) {
        s0 += __shfl_down_sync(0xffffffffu, s0, off);
        s1 += __shfl_down_sync(0xffffffffu, s1, off);
        s2 += __shfl_down_sync(0xffffffffu, s2, off);
        s3 += __shfl_down_sync(0xffffffffu, s3, off);
    }
    int warp = c >> 5, lane = c & 31;
    if (lane == 0) { red[0][warp] = s0; red[1][warp] = s1; red[2][warp] = s2; red[3][warp] = s3; }
    __syncthreads();
    float sf = 0.f, sf2 = 0.f, sb = 0.f, sb2 = 0.f;
#pragma unroll
    for (int wv = 0; wv < 8; wv++) {
        sf += red[0][wv]; sf2 += red[1][wv]; sb += red[2][wv]; sb2 += red[3][wv];
    }
    const float inv = 1.f / 256.f;
    float muf = sf * inv, varf = sf2 * inv - muf * muf;
    float mub = sb * inv, varb = sb2 * inv - mub * mub;
    float nf = (vf - muf) * rsqrtf(varf + 1e-5f) * gf[c] + bef[c];
    float nb = (vb - mub) * rsqrtf(varb + 1e-5f) * gb[c] + beb[c];
    float v = nf + nb;
    if (up) {
        int i = l / dstW, j = l - (l / dstW) * dstW;
        v += up[((long long)b * upSrcW * upSrcW + (i >> 1) * upSrcW + (j >> 1)) * 256 + c];
    }
    if (z) {
        float zz = z[(long long)bl * 512 + 256 + c];
        v *= zz / (1.f + __expf(-zz));
    }
    out[idx] = v;
}

// ---------------- launch ----------------
extern "C" void kernel_launch(void* const* d_in, const int* in_sizes, int n_in,
                              void* d_out, int out_size)
{
    const float* input_f = (const float*)d_in[0];
    const float* in_w  = (const float*)d_in[1];
    const float* in_b  = (const float*)d_in[2];
    const float* c1_w  = (const float*)d_in[3];
    const float* c1_b  = (const float*)d_in[4];
    const float* c2_w  = (const float*)d_in[5];
    const float* c2_b  = (const float*)d_in[6];
    const float* c3_w  = (const float*)d_in[7];
    const float* c3_b  = (const float*)d_in[8];
    const float* out_w = (const float*)d_in[9];
    const float* out_b = (const float*)d_in[10];
    const float* xw1  = (const float*)d_in[11];
    const float* dtw1 = (const float*)d_in[12];
    const float* dtb1 = (const float*)d_in[13];
    const float* Al1  = (const float*)d_in[14];
    const float* Dv1  = (const float*)d_in[15];
    const float* g1   = (const float*)d_in[16];
    const float* be1  = (const float*)d_in[17];
    const float* xw2  = (const float*)d_in[18];
    const float* dtw2 = (const float*)d_in[19];
    const float* dtb2 = (const float*)d_in[20];
    const float* Al2  = (const float*)d_in[21];
    const float* Dv2  = (const float*)d_in[22];
    const float* g2   = (const float*)d_in[23];
    const float* be2  = (const float*)d_in[24];
    const float* xw3  = (const float*)d_in[25];
    const float* dtw3 = (const float*)d_in[26];
    const float* dtb3 = (const float*)d_in[27];
    const float* Al3  = (const float*)d_in[28];
    const float* Dv3  = (const float*)d_in[29];
    const float* g3   = (const float*)d_in[30];
    const float* be3  = (const float*)d_in[31];

    static float *p_xz = nullptr, *p_f1, *p_f2, *p_f3, *p_w2t, *p_w3t,
                 *p_xd1f, *p_xd1b, *p_xd2, *p_xd3,
                 *p_q1f, *p_dx1f, *p_q1b, *p_dx1b, *p_q2, *p_dx2, *p_q3, *p_dx3,
                 *p_yf1, *p_yb1, *p_yf2, *p_yb2, *p_yf3, *p_yb3,
                 *p_y3, *p_y2, *p_y1m;
    if (!p_xz) {
        cudaGetSymbolAddress((void**)&p_xz,  g_xz);
        cudaGetSymbolAddress((void**)&p_f1,  g_f1);
        cudaGetSymbolAddress((void**)&p_f2,  g_f2);
        cudaGetSymbolAddress((void**)&p_f3,  g_f3);
        cudaGetSymbolAddress((void**)&p_w2t, g_w2t);
        cudaGetSymbolAddress((void**)&p_w3t, g_w3t);
        cudaGetSymbolAddress((void**)&p_xd1f, g_xd1f);
        cudaGetSymbolAddress((void**)&p_xd1b, g_xd1b);
        cudaGetSymbolAddress((void**)&p_xd2, g_xd2);
        cudaGetSymbolAddress((void**)&p_xd3, g_xd3);
        cudaGetSymbolAddress((void**)&p_q1f, g_q1f);
        cudaGetSymbolAddress((void**)&p_dx1f, g_dx1f);
        cudaGetSymbolAddress((void**)&p_q1b, g_q1b);
        cudaGetSymbolAddress((void**)&p_dx1b, g_dx1b);
        cudaGetSymbolAddress((void**)&p_q2, g_q2);
        cudaGetSymbolAddress((void**)&p_dx2, g_dx2);
        cudaGetSymbolAddress((void**)&p_q3, g_q3);
        cudaGetSymbolAddress((void**)&p_dx3, g_dx3);
        cudaGetSymbolAddress((void**)&p_yf1, g_yf1);
        cudaGetSymbolAddress((void**)&p_yb1, g_yb1);
        cudaGetSymbolAddress((void**)&p_yf2, g_yf2);
        cudaGetSymbolAddress((void**)&p_yb2, g_yb2);
        cudaGetSymbolAddress((void**)&p_yf3, g_yf3);
        cudaGetSymbolAddress((void**)&p_yb3, g_yb3);
        cudaGetSymbolAddress((void**)&p_y3,  g_y3);
        cudaGetSymbolAddress((void**)&p_y2,  g_y2);
        cudaGetSymbolAddress((void**)&p_y1m, g_y1m);
    }

    wtrans<<<256, 256>>>(c2_w, p_w2t);
    wtrans<<<256, 256>>>(c3_w, p_w3t);

    // 1) in-proj
    gemm_k<1, 0><<<dim3(4, 128, 1), 256>>>(
        input_f, 0, (long long)512 * 1024, 0, 0,
        in_w, 512, in_b, p_xz, 512, 512);

    // 2) c1
    gemm_k<0, 0><<<dim3(2, 128, 1), 256>>>(
        p_xz, 512, 0, 0, 0,
        c1_w, 256, c1_b, p_f1, 256, 256);

    // 3) conv1 (32->16)
    fill_bias<<<NB * L2V, 256>>>(p_f2, c2_b);
    gemm_k<2, 1><<<dim3(2, 32, 8), 256>>>(
        p_f1, 0, 0, 32, 16,
        p_w2t, 1024, nullptr, p_f2, 256, 128);

    // 4) conv2 (16->8)
    fill_bias<<<NB * L3V, 256>>>(p_f3, c3_b);
    gemm_k<2, 1><<<dim3(2, 8, 16), 256>>>(
        p_f2, 0, 0, 16, 8,
        p_w3t, 1024, nullptr, p_f3, 256, 64);

    // 5) xd + q/dxv precompute (level-1 backward uses param set 2 — reference quirk)
    xdq_kernel<<<NB * L1V, 256>>>(p_f1,
        xw1, dtw1, dtb1, xw2, dtw2, dtb2,
        p_xd1f, p_q1f, p_dx1f, p_xd1b, p_q1b, p_dx1b);
    xdq_kernel<<<NB * L2V, 256>>>(p_f2,
        xw2, dtw2, dtb2, nullptr, nullptr, nullptr,
        p_xd2, p_q2, p_dx2, nullptr, nullptr, nullptr);
    xdq_kernel<<<NB * L3V, 256>>>(p_f3,
        xw3, dtw3, dtb3, nullptr, nullptr, nullptr,
        p_xd3, p_q3, p_dx3, nullptr, nullptr, nullptr);

    // 6) segmented scans
    scanA_kernel<<<512, 32>>>(Al1, Al2);
    scanB_kernel<<<896, 32>>>(Dv1, Dv2, Dv3, Al1, Al2, Al3);

    // 7-9) layernorm / upsample / gate chain
    ln_kernel<<<NB * L3V, 256>>>(p_yf3, p_yb3, g3, be3, g3, be3,
                                 nullptr, 0, 0, nullptr, p_y3, L3V);
    ln_kernel<<<NB * L2V, 256>>>(p_yf2, p_yb2, g2, be2, g2, be2,
                                 p_y3, 8, 16, nullptr, p_y2, L2V);
    ln_kernel<<<NB * L1V, 256>>>(p_yf1, p_yb1, g1, be1, g2, be2,
                                 p_y2, 16, 32, p_xz, p_y1m, L1V);

    // 10) out-proj (roles swapped, coalesced CHW store)
    gemm_k<0, 2><<<dim3(64, 8, 1), 256>>>(
        out_w, 256, 0, 0, 0,
        p_y1m, 256, out_b, (float*)d_out, 8192, 256);
}